// round 15
// baseline (speedup 1.0000x reference)
#include <cuda_runtime.h>
#include <cuda_bf16.h>
#include <cuda_fp16.h>
#include <math.h>
#include <stdint.h>

// ---------------------------------------------------------------------------
// Problem constants
// ---------------------------------------------------------------------------
#define BB   512
#define HH   128
#define WW   128
#define CONVN 16129
#define DIM  4096
#define KDIM 4096
#define OUTN (BB * DIM)

// ---------------------------------------------------------------------------
// Scratch (__device__ globals; no cudaMalloc allowed)
// ---------------------------------------------------------------------------
__device__ float g_c[BB];
__device__ __half g_ah[4][OUTN];      // fp16 act1..act4
#define FID_BLOCKS 512
__device__ float g_partials[FID_BLOCKS * 10];
__device__ unsigned int g_ticket;     // zero-init; reset by winning block

// ---------------------------------------------------------------------------
// PTX helpers (plain-PTX, valid on non-'a' targets)
// ---------------------------------------------------------------------------
__device__ __forceinline__ uint32_t smem_to_u32(const void* p) {
    uint32_t a;
    asm("{ .reg .u64 t; cvta.to.shared.u64 t, %1; cvt.u32.u64 %0, t; }"
        : "=r"(a) : "l"(p));
    return a;
}
__device__ __forceinline__ void cpasync16(uint32_t dst, const void* gsrc) {
    asm volatile("cp.async.cg.shared.global [%0], [%1], 16;"
                 :: "r"(dst), "l"(__cvta_generic_to_global(gsrc)) : "memory");
}
#define CP_COMMIT() asm volatile("cp.async.commit_group;" ::: "memory")
template <int N>
__device__ __forceinline__ void cp_wait() {
    asm volatile("cp.async.wait_group %0;" :: "n"(N) : "memory");
}
__device__ __forceinline__ void ldsm_x4(uint32_t r[4], uint32_t addr) {
    asm volatile("ldmatrix.sync.aligned.m8n8.x4.shared.b16 {%0,%1,%2,%3}, [%4];"
                 : "=r"(r[0]), "=r"(r[1]), "=r"(r[2]), "=r"(r[3]) : "r"(addr));
}
__device__ __forceinline__ void mma16816h(float d[4], const uint32_t a[4],
                                          uint32_t b0, uint32_t b1) {
    asm volatile(
        "mma.sync.aligned.m16n8k16.row.col.f32.f16.f16.f32 "
        "{%0,%1,%2,%3}, {%4,%5,%6,%7}, {%8,%9}, {%0,%1,%2,%3};"
        : "+f"(d[0]), "+f"(d[1]), "+f"(d[2]), "+f"(d[3])
        : "r"(a[0]), "r"(a[1]), "r"(a[2]), "r"(a[3]), "r"(b0), "r"(b1));
}
__device__ __forceinline__ float tanh_approx(float x) {
    float r;
    asm("tanh.approx.f32 %0, %1;" : "=f"(r) : "f"(x));
    return r;
}

// ---------------------------------------------------------------------------
// 1) Conv 2x2 valid + bias + sigmoid + mean -> g_c[n]
//    Manual 2x unroll: both idx groups' loads issued before compute (MLP).
//    Accumulation order preserved (idx, then idx+256) -> bitwise identical.
// ---------------------------------------------------------------------------
__global__ void __launch_bounds__(256)
conv_kernel(const float* __restrict__ x,
            const float* __restrict__ cw,
            const float* __restrict__ cb,
            float* __restrict__ cOut) {
    const int n = blockIdx.x;
    const float* xp = x + n * HH * WW;
    const float w00 = 0.5f * cw[0], w01 = 0.5f * cw[1];
    const float w10 = 0.5f * cw[2], w11 = 0.5f * cw[3];
    const float bias = 0.5f * cb[0];
    float s = 0.0f;

    // 127*32 = 4064 groups; 256 threads -> pairs (idx, idx+256), 8 pairs covers
    // idx in [0, 4096); guard both.
    for (int base = threadIdx.x; base < 127 * 32; base += 512) {
        const int idxA = base;
        const int idxB = base + 256;
        const bool hasB = idxB < 127 * 32;

        const int iA = idxA >> 5, jA = (idxA & 31) * 4;
        const float* a0 = xp + iA * WW + jA;
        const float* a1 = a0 + WW;
        float4 ra0 = *(const float4*)a0;
        float4 ra1 = *(const float4*)a1;
        float a4 = 0.0f, b4 = 0.0f;
        if (jA + 4 < WW) { a4 = a0[4]; b4 = a1[4]; }

        int iB = 0, jB = 0;
        float4 rb0 = make_float4(0, 0, 0, 0), rb1 = make_float4(0, 0, 0, 0);
        float c4 = 0.0f, d4 = 0.0f;
        if (hasB) {
            iB = idxB >> 5; jB = (idxB & 31) * 4;
            const float* p0 = xp + iB * WW + jB;
            const float* p1 = p0 + WW;
            rb0 = *(const float4*)p0;
            rb1 = *(const float4*)p1;
            if (jB + 4 < WW) { c4 = p0[4]; d4 = p1[4]; }
        }

        {
            float x0[5] = {ra0.x, ra0.y, ra0.z, ra0.w, a4};
            float x1[5] = {ra1.x, ra1.y, ra1.z, ra1.w, b4};
            #pragma unroll
            for (int k = 0; k < 4; k++) {
                if (jA + k < 127) {
                    float hv = x0[k] * w00 + x0[k + 1] * w01
                             + x1[k] * w10 + x1[k + 1] * w11 + bias;
                    s += tanh_approx(hv);
                }
            }
        }
        if (hasB) {
            float x0[5] = {rb0.x, rb0.y, rb0.z, rb0.w, c4};
            float x1[5] = {rb1.x, rb1.y, rb1.z, rb1.w, d4};
            #pragma unroll
            for (int k = 0; k < 4; k++) {
                if (jB + k < 127) {
                    float hv = x0[k] * w00 + x0[k + 1] * w01
                             + x1[k] * w10 + x1[k + 1] * w11 + bias;
                    s += tanh_approx(hv);
                }
            }
        }
    }

    __shared__ float red[256];
    red[threadIdx.x] = s;
    __syncthreads();
    #pragma unroll
    for (int off = 128; off > 0; off >>= 1) {
        if (threadIdx.x < off) red[threadIdx.x] += red[threadIdx.x + off];
        __syncthreads();
    }
    if (threadIdx.x == 0)
        cOut[n] = 0.5f + 0.5f * (red[0] / (float)CONVN);
}

// ---------------------------------------------------------------------------
// 2) Fused attention + Layer 1 -> fp16 act1.  8 outputs/thread, uint4 stores.
// ---------------------------------------------------------------------------
__global__ void attn_layer1_kernel(const float* __restrict__ c,
                                   const float* __restrict__ rot,
                                   const float* __restrict__ ent,
                                   const float* __restrict__ W1,
                                   const float* __restrict__ b1,
                                   __half* __restrict__ oh) {
    const int i = blockIdx.x >> 1;
    const int j0 = (blockIdx.x & 1) * 2048 + threadIdx.x * 8;
    const int t = threadIdx.x;

    __shared__ float cs[BB];
    __shared__ float wred[8][2];
    __shared__ float aI;

    cs[t] = c[t];
    cs[t + 256] = c[t + 256];
    __syncthreads();

    const float e = ent[0];
    const float qi = cs[i] * rot[0];

    float v0 = qi * cs[t] * e, v1 = qi * cs[t + 256] * e;
    float mx = fmaxf(v0, v1);
    #pragma unroll
    for (int off = 16; off > 0; off >>= 1)
        mx = fmaxf(mx, __shfl_xor_sync(0xFFFFFFFFu, mx, off));
    if ((t & 31) == 0) wred[t >> 5][0] = mx;
    __syncthreads();
    float m = wred[0][0];
    #pragma unroll
    for (int w = 1; w < 8; w++) m = fmaxf(m, wred[w][0]);

    float e0 = __expf(v0 - m), e1 = __expf(v1 - m);
    float se = e0 + e1;
    float sa = e0 * cs[t] + e1 * cs[t + 256];
    #pragma unroll
    for (int off = 16; off > 0; off >>= 1) {
        se += __shfl_xor_sync(0xFFFFFFFFu, se, off);
        sa += __shfl_xor_sync(0xFFFFFFFFu, sa, off);
    }
    if ((t & 31) == 0) { wred[t >> 5][0] = se; wred[t >> 5][1] = sa; }
    __syncthreads();
    if (t == 0) {
        float tse = 0.0f, tsa = 0.0f;
        #pragma unroll
        for (int w = 0; w < 8; w++) { tse += wred[w][0]; tsa += wred[w][1]; }
        aI = tsa / tse;
    }
    __syncthreads();

    const float a = aI;
    float4 wv0 = *(const float4*)(W1 + j0);
    float4 wv1 = *(const float4*)(W1 + j0 + 4);
    float4 bv0 = *(const float4*)(b1 + j0);
    float4 bv1 = *(const float4*)(b1 + j0 + 4);
    float o[8];
    o[0] = tanhf(fmaf(a, wv0.x, bv0.x));
    o[1] = tanhf(fmaf(a, wv0.y, bv0.y));
    o[2] = tanhf(fmaf(a, wv0.z, bv0.z));
    o[3] = tanhf(fmaf(a, wv0.w, bv0.w));
    o[4] = tanhf(fmaf(a, wv1.x, bv1.x));
    o[5] = tanhf(fmaf(a, wv1.y, bv1.y));
    o[6] = tanhf(fmaf(a, wv1.z, bv1.z));
    o[7] = tanhf(fmaf(a, wv1.w, bv1.w));
    __half2 h0 = __floats2half2_rn(o[0], o[1]);
    __half2 h1 = __floats2half2_rn(o[2], o[3]);
    __half2 h2 = __floats2half2_rn(o[4], o[5]);
    __half2 h3 = __floats2half2_rn(o[6], o[7]);
    uint4 pack;
    pack.x = *(uint32_t*)&h0; pack.y = *(uint32_t*)&h1;
    pack.z = *(uint32_t*)&h2; pack.w = *(uint32_t*)&h3;
    *(uint4*)(oh + (size_t)i * DIM + j0) = pack;
}

// ---------------------------------------------------------------------------
// 3) HMMA GEMM + bias + tanh; in-kernel W fp32->fp16; ONE sync per 2 kt.
//    (R12/R14 schedule; full drain only on the FINAL epoch.)
// ---------------------------------------------------------------------------
#define KT      64
#define NT      (KDIM / KT)             // 64
#define SROW    72                      // padded row stride in halves (144 B)
#define TILE_B  (128 * SROW * 2)        // 18432 B
#define NASLOT  6
#define WF_OFF  (NASLOT * TILE_B)       // 110592
#define BIAS_OFF (WF_OFF + 4 * TILE_B)  // 184320
#define SMEM_REQ (BIAS_OFF + 512)

__global__ void __launch_bounds__(512, 1)
gemm_mma_kernel(const __half* __restrict__ Ah,
                const float* __restrict__ W,   // fp32 weights, row-major
                const float* __restrict__ bias,
                float* __restrict__ C,         // may be null
                __half* __restrict__ Ch) {
    extern __shared__ __align__(16) char smem[];
    const uint32_t sbase = smem_to_u32(smem);
    float* biasS = (float*)(smem + BIAS_OFF);

    const int t = threadIdx.x;
    const int lane = t & 31;
    const int warp = t >> 5;            // 0..15
    const int mw = warp >> 2;           // 0..3
    const int nw = warp & 3;            // 0..3
    const int M0 = mw * 32;
    const int N0 = nw * 32;
    const int m0 = blockIdx.y * 128;
    const int n0 = blockIdx.x * 128;

    if (t < 128) biasS[t] = bias[n0 + t];

    const __half* Ag = Ah + (size_t)m0 * KDIM;
    const float*  Wg = W  + (size_t)n0 * KDIM;

    #define ISSUE_A(ktv, slot) do {                                            \
        const int _kt = (ktv);                                                 \
        const uint32_t _stg = sbase + (uint32_t)(slot) * TILE_B;               \
        _Pragma("unroll")                                                      \
        for (int _i = 0; _i < 2; _i++) {                                       \
            const int _c = _i * 512 + t;                                       \
            const int _r = _c >> 3;                                            \
            const int _c16 = _c & 7;                                           \
            cpasync16(_stg + (uint32_t)(_r * SROW + _c16 * 8) * 2,             \
                      Ag + (size_t)_r * KDIM + _kt * KT + _c16 * 8);           \
        }                                                                      \
    } while (0)

    const int rowL = t >> 4;   // 0..31
    const int col4 = t & 15;   // 0..15
    float4 wreg[4];

    #define LOAD_W(ktv) do {                                                   \
        _Pragma("unroll")                                                      \
        for (int _i = 0; _i < 4; _i++)                                         \
            wreg[_i] = *(const float4*)(Wg + (size_t)(rowL + 32 * _i) * KDIM   \
                                        + (ktv) * KT + col4 * 4);              \
    } while (0)

    #define STS_W(buf) do {                                                    \
        _Pragma("unroll")                                                      \
        for (int _i = 0; _i < 4; _i++) {                                       \
            __half2 _h0 = __floats2half2_rn(wreg[_i].x, wreg[_i].y);           \
            __half2 _h1 = __floats2half2_rn(wreg[_i].z, wreg[_i].w);           \
            uint32_t _ad = sbase + WF_OFF + (uint32_t)(buf) * TILE_B           \
                         + (uint32_t)((rowL + 32 * _i) * SROW + col4 * 4) * 2; \
            asm volatile("st.shared.v2.u32 [%0], {%1, %2};" :: "r"(_ad),       \
                         "r"(*(uint32_t*)&_h0), "r"(*(uint32_t*)&_h1));        \
        }                                                                      \
    } while (0)

    // Prologue: A stages 0..3; W slots 0,1 + regs hold W(2)
    ISSUE_A(0, 0); CP_COMMIT();
    ISSUE_A(1, 1); CP_COMMIT();
    ISSUE_A(2, 2); CP_COMMIT();
    ISSUE_A(3, 3); CP_COMMIT();
    LOAD_W(0); STS_W(0);
    LOAD_W(1); STS_W(1);
    LOAD_W(2);

    // ldmatrix lane addressing
    const int g = lane >> 3, rin = lane & 7;
    const int rowA = M0 + (g & 1) * 8 + rin;
    const int colA = (g >> 1) * 8;
    const int rowB = N0 + (g >> 1) * 8 + rin;
    const int colB = (g & 1) * 8;

    float acc[2][4][4];
    #pragma unroll
    for (int i = 0; i < 2; i++)
        #pragma unroll
        for (int j = 0; j < 4; j++)
            #pragma unroll
            for (int k = 0; k < 4; k++) acc[i][j][k] = 0.0f;

    uint32_t aF[2][2][4], bF[2][2][4];

    #define LOADH(hh, buf, bAv, bWv) do {                                      \
        const int _kc = (hh) * 16;                                             \
        _Pragma("unroll")                                                      \
        for (int _mi = 0; _mi < 2; _mi++)                                      \
            ldsm_x4(aF[buf][_mi],                                              \
                    (bAv) + (uint32_t)((rowA + _mi * 16) * SROW + _kc + colA) * 2); \
        _Pragma("unroll")                                                      \
        for (int _j = 0; _j < 2; _j++)                                         \
            ldsm_x4(bF[buf][_j],                                               \
                    (bWv) + (uint32_t)((rowB + _j * 16) * SROW + _kc + colB) * 2);  \
    } while (0)

    #define COMPUTE_TILE(slotA, slotW) do {                                    \
        const uint32_t _bA = sbase + (uint32_t)(slotA) * TILE_B;               \
        const uint32_t _bW = sbase + WF_OFF + (uint32_t)(slotW) * TILE_B;      \
        LOADH(0, 0, _bA, _bW);                                                 \
        _Pragma("unroll")                                                      \
        for (int _h = 0; _h < 4; _h++) {                                       \
            const int _cur = _h & 1;                                           \
            if (_h < 3) LOADH(_h + 1, _cur ^ 1, _bA, _bW);                     \
            _Pragma("unroll")                                                  \
            for (int _mi = 0; _mi < 2; _mi++)                                  \
                _Pragma("unroll")                                              \
                for (int _nj = 0; _nj < 4; _nj++) {                            \
                    const int _jj = _nj >> 1, _pp = (_nj & 1) * 2;             \
                    mma16816h(acc[_mi][_nj], aF[_cur][_mi],                    \
                              bF[_cur][_jj][_pp], bF[_cur][_jj][_pp + 1]);     \
                }                                                              \
        }                                                                      \
    } while (0)

    int sA0 = 0, sA1 = 1, iA0 = 4, iA1 = 5;
    for (int kt = 0; kt < NT; kt += 2) {
        // wait<2> is safe for every epoch except the final one (outstanding
        // groups then are exactly the two still needed).
        if (kt + 2 >= NT) cp_wait<0>(); else cp_wait<2>();
        __syncthreads();   // publishes A[kt],A[kt+1] + W slots (kt&3),(kt+1)&3
        if (kt + 4 < NT) { ISSUE_A(kt + 4, iA0); CP_COMMIT(); }
        if (kt + 5 < NT) { ISSUE_A(kt + 5, iA1); CP_COMMIT(); }

        COMPUTE_TILE(sA0, kt & 3);
        if (kt + 2 < NT) {
            STS_W((kt + 2) & 3);   // wreg holds W(kt+2)
            LOAD_W(kt + 3);
        }
        COMPUTE_TILE(sA1, (kt + 1) & 3);
        if (kt + 2 < NT) STS_W((kt + 3) & 3);
        if (kt + 4 < NT) LOAD_W(kt + 4);

        sA0 += 2; if (sA0 >= NASLOT) sA0 -= NASLOT;
        sA1 += 2; if (sA1 >= NASLOT) sA1 -= NASLOT;
        iA0 += 2; if (iA0 >= NASLOT) iA0 -= NASLOT;
        iA1 += 2; if (iA1 >= NASLOT) iA1 -= NASLOT;
    }

    // epilogue: bias + tanh -> fp16 Ch (+ fp32 C if requested)
    const int r0l = lane >> 2;
    const int c0l = 2 * (lane & 3);
    #pragma unroll
    for (int mi = 0; mi < 2; mi++) {
        #pragma unroll
        for (int nj = 0; nj < 4; nj++) {
            const int gnl = N0 + nj * 8 + c0l;
            const float b0 = biasS[gnl], b1 = biasS[gnl + 1];
            const int gm0 = m0 + M0 + mi * 16 + r0l;
            float v00 = tanhf(acc[mi][nj][0] + b0);
            float v01 = tanhf(acc[mi][nj][1] + b1);
            float v10 = tanhf(acc[mi][nj][2] + b0);
            float v11 = tanhf(acc[mi][nj][3] + b1);
            *(__half2*)(Ch + (size_t)gm0 * DIM + n0 + gnl) =
                __floats2half2_rn(v00, v01);
            *(__half2*)(Ch + (size_t)(gm0 + 8) * DIM + n0 + gnl) =
                __floats2half2_rn(v10, v11);
            if (C != nullptr) {
                *(float2*)(C + (size_t)gm0 * DIM + n0 + gnl) = make_float2(v00, v01);
                *(float2*)(C + (size_t)(gm0 + 8) * DIM + n0 + gnl) = make_float2(v10, v11);
            }
        }
    }
}

// ---------------------------------------------------------------------------
// 4) Fused fidelity: 10 dots (fp32) + last-block finalize (ticket pattern).
// ---------------------------------------------------------------------------
__global__ void fid_kernel(const __half* __restrict__ a1,
                           const __half* __restrict__ a2,
                           const __half* __restrict__ a3,
                           const __half* __restrict__ a4,
                           float* __restrict__ wout) {
    float s[10];
    #pragma unroll
    for (int k = 0; k < 10; k++) s[k] = 0.0f;
    const int stride = gridDim.x * blockDim.x;
    for (int idx = blockIdx.x * blockDim.x + threadIdx.x; idx < OUTN / 2; idx += stride) {
        float2 f1 = __half22float2(((const __half2*)a1)[idx]);
        float2 f2 = __half22float2(((const __half2*)a2)[idx]);
        float2 f3 = __half22float2(((const __half2*)a3)[idx]);
        float2 f4 = __half22float2(((const __half2*)a4)[idx]);
        s[0] += f1.x * f1.x + f1.y * f1.y;
        s[1] += f1.x * f2.x + f1.y * f2.y;
        s[2] += f1.x * f3.x + f1.y * f3.y;
        s[3] += f1.x * f4.x + f1.y * f4.y;
        s[4] += f2.x * f2.x + f2.y * f2.y;
        s[5] += f2.x * f3.x + f2.y * f3.y;
        s[6] += f2.x * f4.x + f2.y * f4.y;
        s[7] += f3.x * f3.x + f3.y * f3.y;
        s[8] += f3.x * f4.x + f3.y * f4.y;
        s[9] += f4.x * f4.x + f4.y * f4.y;
    }
    #pragma unroll
    for (int k = 0; k < 10; k++)
        #pragma unroll
        for (int off = 16; off > 0; off >>= 1)
            s[k] += __shfl_down_sync(0xFFFFFFFFu, s[k], off);
    __shared__ float ws[8][10];
    const int wid = threadIdx.x >> 5, lid = threadIdx.x & 31;
    if (lid == 0)
        #pragma unroll
        for (int k = 0; k < 10; k++) ws[wid][k] = s[k];
    __syncthreads();

    __shared__ unsigned int lastFlag;
    if (threadIdx.x == 0) {
        #pragma unroll
        for (int k = 0; k < 10; k++) {
            float acc = 0.0f;
            for (int w = 0; w < 8; w++) acc += ws[w][k];
            g_partials[blockIdx.x * 10 + k] = acc;
        }
        __threadfence();
        unsigned int v = atomicAdd(&g_ticket, 1u);
        lastFlag = (v == gridDim.x - 1) ? 1u : 0u;
    }
    __syncthreads();
    if (lastFlag == 0u) return;

    __shared__ double dots[10];
    #pragma unroll
    for (int pass = 0; pass < 2; pass++) {
        int d = pass == 0 ? wid : (wid < 2 ? 8 + wid : -1);
        if (pass == 1 && wid >= 2) break;
        if (d >= 0 && d < 10) {
            double acc = 0.0;
            for (int p = lid; p < FID_BLOCKS; p += 32)
                acc += (double)g_partials[p * 10 + d];
            #pragma unroll
            for (int off = 16; off > 0; off >>= 1)
                acc += __shfl_down_sync(0xFFFFFFFFu, acc, off);
            if (lid == 0) dots[d] = acc;
        }
    }
    __syncthreads();
    if (threadIdx.x < 16) {
        int i = threadIdx.x >> 2, j = threadIdx.x & 3;
        int ii = i < j ? i : j, jj = i < j ? j : i;
        const int base[4] = {0, 4, 7, 9};
        double dij = dots[base[ii] + (jj - ii)];
        double dii = dots[base[ii]];
        double djj = dots[base[jj]];
        double ni = sqrt(dii) + 1e-12;
        double nj = sqrt(djj) + 1e-12;
        double sh = dij / (ni * nj);
        double fid = sh * sh;
        wout[threadIdx.x] = (fid >= 0.8 && i != j) ? 1.0f : 0.0f;
    }
    if (threadIdx.x == 0) g_ticket = 0u;   // reset for next graph replay
}

// ---------------------------------------------------------------------------
// kernel_launch
//   0 conv, 1 attn_layer1, 2 gemm1, 3 gemm2, 4 gemm3, 5 fid <- profiled
// ---------------------------------------------------------------------------
extern "C" void kernel_launch(void* const* d_in, const int* in_sizes, int n_in,
                              void* d_out, int out_size) {
    const float* x   = (const float*)d_in[0];
    const float* cw  = (const float*)d_in[1];
    const float* cb  = (const float*)d_in[2];
    const float* rot = (const float*)d_in[3];
    const float* ent = (const float*)d_in[4];
    const float* W1  = (const float*)d_in[5];
    const float* b1  = (const float*)d_in[6];
    const float* W2  = (const float*)d_in[7];
    const float* b2  = (const float*)d_in[8];
    const float* W3  = (const float*)d_in[9];
    const float* b3  = (const float*)d_in[10];
    const float* W4  = (const float*)d_in[11];
    const float* b4  = (const float*)d_in[12];
    float* out = (float*)d_out;

    float* gc;
    __half* ah;
    cudaGetSymbolAddress((void**)&gc, g_c);
    cudaGetSymbolAddress((void**)&ah, g_ah);

    cudaFuncSetAttribute(gemm_mma_kernel,
                         cudaFuncAttributeMaxDynamicSharedMemorySize, SMEM_REQ);

    dim3 ggrid(DIM / 128, BB / 128);  // (32, 4)

    conv_kernel<<<BB, 256>>>(x, cw, cb, gc);                         // 0
    attn_layer1_kernel<<<1024, 256>>>(gc, rot, ent, W1, b1,          // 1
                                      ah + 0 * (size_t)OUTN);
    gemm_mma_kernel<<<ggrid, 512, SMEM_REQ>>>(                       // 2
        ah + 0 * (size_t)OUTN, W2, b2,
        nullptr, ah + 1 * (size_t)OUTN);
    gemm_mma_kernel<<<ggrid, 512, SMEM_REQ>>>(                       // 3
        ah + 1 * (size_t)OUTN, W3, b3,
        nullptr, ah + 2 * (size_t)OUTN);
    gemm_mma_kernel<<<ggrid, 512, SMEM_REQ>>>(                       // 4
        ah + 2 * (size_t)OUTN, W4, b4,
        out, ah + 3 * (size_t)OUTN);
    fid_kernel<<<FID_BLOCKS, 256>>>(ah + 0 * (size_t)OUTN,           // 5 <- profiled
                                    ah + 1 * (size_t)OUTN,
                                    ah + 2 * (size_t)OUTN,
                                    ah + 3 * (size_t)OUTN,
                                    out + OUTN);
}

// round 16
// speedup vs baseline: 1.0058x; 1.0058x over previous
#include <cuda_runtime.h>
#include <cuda_bf16.h>
#include <cuda_fp16.h>
#include <math.h>
#include <stdint.h>

// ---------------------------------------------------------------------------
// Problem constants
// ---------------------------------------------------------------------------
#define BB   512
#define HH   128
#define WW   128
#define CONVN 16129
#define DIM  4096
#define KDIM 4096
#define OUTN (BB * DIM)

// ---------------------------------------------------------------------------
// Scratch (__device__ globals; no cudaMalloc allowed)
// ---------------------------------------------------------------------------
__device__ float g_c[BB];
__device__ __half g_ah[4][OUTN];      // fp16 act1..act4
#define FID_BLOCKS 512
__device__ float g_partials[FID_BLOCKS * 10];
__device__ unsigned int g_ticket;     // zero-init; reset by winning block

// ---------------------------------------------------------------------------
// PTX helpers (plain-PTX, valid on non-'a' targets)
// ---------------------------------------------------------------------------
__device__ __forceinline__ uint32_t smem_to_u32(const void* p) {
    uint32_t a;
    asm("{ .reg .u64 t; cvta.to.shared.u64 t, %1; cvt.u32.u64 %0, t; }"
        : "=r"(a) : "l"(p));
    return a;
}
__device__ __forceinline__ void cpasync16(uint32_t dst, const void* gsrc) {
    asm volatile("cp.async.cg.shared.global [%0], [%1], 16;"
                 :: "r"(dst), "l"(__cvta_generic_to_global(gsrc)) : "memory");
}
#define CP_COMMIT() asm volatile("cp.async.commit_group;" ::: "memory")
template <int N>
__device__ __forceinline__ void cp_wait() {
    asm volatile("cp.async.wait_group %0;" :: "n"(N) : "memory");
}
__device__ __forceinline__ void ldsm_x4(uint32_t r[4], uint32_t addr) {
    asm volatile("ldmatrix.sync.aligned.m8n8.x4.shared.b16 {%0,%1,%2,%3}, [%4];"
                 : "=r"(r[0]), "=r"(r[1]), "=r"(r[2]), "=r"(r[3]) : "r"(addr));
}
__device__ __forceinline__ void mma16816h(float d[4], const uint32_t a[4],
                                          uint32_t b0, uint32_t b1) {
    asm volatile(
        "mma.sync.aligned.m16n8k16.row.col.f32.f16.f16.f32 "
        "{%0,%1,%2,%3}, {%4,%5,%6,%7}, {%8,%9}, {%0,%1,%2,%3};"
        : "+f"(d[0]), "+f"(d[1]), "+f"(d[2]), "+f"(d[3])
        : "r"(a[0]), "r"(a[1]), "r"(a[2]), "r"(a[3]), "r"(b0), "r"(b1));
}
__device__ __forceinline__ float tanh_approx(float x) {
    float r;
    asm("tanh.approx.f32 %0, %1;" : "=f"(r) : "f"(x));
    return r;
}

// ---------------------------------------------------------------------------
// 1) Conv 2x2 valid + bias + sigmoid + mean -> g_c[n]
// ---------------------------------------------------------------------------
__global__ void __launch_bounds__(256)
conv_kernel(const float* __restrict__ x,
            const float* __restrict__ cw,
            const float* __restrict__ cb,
            float* __restrict__ cOut) {
    const int n = blockIdx.x;
    const float* xp = x + n * HH * WW;
    const float w00 = 0.5f * cw[0], w01 = 0.5f * cw[1];
    const float w10 = 0.5f * cw[2], w11 = 0.5f * cw[3];
    const float bias = 0.5f * cb[0];
    float s = 0.0f;
    for (int idx = threadIdx.x; idx < 127 * 32; idx += 256) {
        const int i = idx >> 5;
        const int j = (idx & 31) * 4;
        const float* r0 = xp + i * WW + j;
        const float* r1 = r0 + WW;
        float4 a = *(const float4*)r0;
        float4 b = *(const float4*)r1;
        float a4 = 0.0f, b4 = 0.0f;
        if (j + 4 < WW) { a4 = r0[4]; b4 = r1[4]; }
        float x0[5] = {a.x, a.y, a.z, a.w, a4};
        float x1[5] = {b.x, b.y, b.z, b.w, b4};
        #pragma unroll
        for (int k = 0; k < 4; k++) {
            if (j + k < 127) {
                float hv = x0[k] * w00 + x0[k + 1] * w01
                         + x1[k] * w10 + x1[k + 1] * w11 + bias;
                s += tanh_approx(hv);
            }
        }
    }
    __shared__ float red[256];
    red[threadIdx.x] = s;
    __syncthreads();
    #pragma unroll
    for (int off = 128; off > 0; off >>= 1) {
        if (threadIdx.x < off) red[threadIdx.x] += red[threadIdx.x + off];
        __syncthreads();
    }
    if (threadIdx.x == 0)
        cOut[n] = 0.5f + 0.5f * (red[0] / (float)CONVN);
}

// ---------------------------------------------------------------------------
// 2) Fused attention + Layer 1 -> fp16 act1.  8 outputs/thread, uint4 stores.
// ---------------------------------------------------------------------------
__global__ void attn_layer1_kernel(const float* __restrict__ c,
                                   const float* __restrict__ rot,
                                   const float* __restrict__ ent,
                                   const float* __restrict__ W1,
                                   const float* __restrict__ b1,
                                   __half* __restrict__ oh) {
    const int i = blockIdx.x >> 1;
    const int j0 = (blockIdx.x & 1) * 2048 + threadIdx.x * 8;
    const int t = threadIdx.x;

    __shared__ float cs[BB];
    __shared__ float wred[8][2];
    __shared__ float aI;

    cs[t] = c[t];
    cs[t + 256] = c[t + 256];
    __syncthreads();

    const float e = ent[0];
    const float qi = cs[i] * rot[0];

    float v0 = qi * cs[t] * e, v1 = qi * cs[t + 256] * e;
    float mx = fmaxf(v0, v1);
    #pragma unroll
    for (int off = 16; off > 0; off >>= 1)
        mx = fmaxf(mx, __shfl_xor_sync(0xFFFFFFFFu, mx, off));
    if ((t & 31) == 0) wred[t >> 5][0] = mx;
    __syncthreads();
    float m = wred[0][0];
    #pragma unroll
    for (int w = 1; w < 8; w++) m = fmaxf(m, wred[w][0]);

    float e0 = __expf(v0 - m), e1 = __expf(v1 - m);
    float se = e0 + e1;
    float sa = e0 * cs[t] + e1 * cs[t + 256];
    #pragma unroll
    for (int off = 16; off > 0; off >>= 1) {
        se += __shfl_xor_sync(0xFFFFFFFFu, se, off);
        sa += __shfl_xor_sync(0xFFFFFFFFu, sa, off);
    }
    if ((t & 31) == 0) { wred[t >> 5][0] = se; wred[t >> 5][1] = sa; }
    __syncthreads();
    if (t == 0) {
        float tse = 0.0f, tsa = 0.0f;
        #pragma unroll
        for (int w = 0; w < 8; w++) { tse += wred[w][0]; tsa += wred[w][1]; }
        aI = tsa / tse;
    }
    __syncthreads();

    const float a = aI;
    float4 wv0 = *(const float4*)(W1 + j0);
    float4 wv1 = *(const float4*)(W1 + j0 + 4);
    float4 bv0 = *(const float4*)(b1 + j0);
    float4 bv1 = *(const float4*)(b1 + j0 + 4);
    float o[8];
    o[0] = tanhf(fmaf(a, wv0.x, bv0.x));
    o[1] = tanhf(fmaf(a, wv0.y, bv0.y));
    o[2] = tanhf(fmaf(a, wv0.z, bv0.z));
    o[3] = tanhf(fmaf(a, wv0.w, bv0.w));
    o[4] = tanhf(fmaf(a, wv1.x, bv1.x));
    o[5] = tanhf(fmaf(a, wv1.y, bv1.y));
    o[6] = tanhf(fmaf(a, wv1.z, bv1.z));
    o[7] = tanhf(fmaf(a, wv1.w, bv1.w));
    __half2 h0 = __floats2half2_rn(o[0], o[1]);
    __half2 h1 = __floats2half2_rn(o[2], o[3]);
    __half2 h2 = __floats2half2_rn(o[4], o[5]);
    __half2 h3 = __floats2half2_rn(o[6], o[7]);
    uint4 pack;
    pack.x = *(uint32_t*)&h0; pack.y = *(uint32_t*)&h1;
    pack.z = *(uint32_t*)&h2; pack.w = *(uint32_t*)&h3;
    *(uint4*)(oh + (size_t)i * DIM + j0) = pack;
}

// ---------------------------------------------------------------------------
// 3) HMMA GEMM + bias + tanh; in-kernel W fp32->fp16; ONE sync per 2 kt.
//    (Best-known R12/R14/R15 schedule; full drain only on the FINAL epoch.)
// ---------------------------------------------------------------------------
#define KT      64
#define NT      (KDIM / KT)             // 64
#define SROW    72                      // padded row stride in halves (144 B)
#define TILE_B  (128 * SROW * 2)        // 18432 B
#define NASLOT  6
#define WF_OFF  (NASLOT * TILE_B)       // 110592
#define BIAS_OFF (WF_OFF + 4 * TILE_B)  // 184320
#define SMEM_REQ (BIAS_OFF + 512)

__global__ void __launch_bounds__(512, 1)
gemm_mma_kernel(const __half* __restrict__ Ah,
                const float* __restrict__ W,   // fp32 weights, row-major
                const float* __restrict__ bias,
                float* __restrict__ C,         // may be null
                __half* __restrict__ Ch) {
    extern __shared__ __align__(16) char smem[];
    const uint32_t sbase = smem_to_u32(smem);
    float* biasS = (float*)(smem + BIAS_OFF);

    const int t = threadIdx.x;
    const int lane = t & 31;
    const int warp = t >> 5;            // 0..15
    const int mw = warp >> 2;           // 0..3
    const int nw = warp & 3;            // 0..3
    const int M0 = mw * 32;
    const int N0 = nw * 32;
    const int m0 = blockIdx.y * 128;
    const int n0 = blockIdx.x * 128;

    if (t < 128) biasS[t] = bias[n0 + t];

    const __half* Ag = Ah + (size_t)m0 * KDIM;
    const float*  Wg = W  + (size_t)n0 * KDIM;

    #define ISSUE_A(ktv, slot) do {                                            \
        const int _kt = (ktv);                                                 \
        const uint32_t _stg = sbase + (uint32_t)(slot) * TILE_B;               \
        _Pragma("unroll")                                                      \
        for (int _i = 0; _i < 2; _i++) {                                       \
            const int _c = _i * 512 + t;                                       \
            const int _r = _c >> 3;                                            \
            const int _c16 = _c & 7;                                           \
            cpasync16(_stg + (uint32_t)(_r * SROW + _c16 * 8) * 2,             \
                      Ag + (size_t)_r * KDIM + _kt * KT + _c16 * 8);           \
        }                                                                      \
    } while (0)

    const int rowL = t >> 4;   // 0..31
    const int col4 = t & 15;   // 0..15
    float4 wreg[4];

    #define LOAD_W(ktv) do {                                                   \
        _Pragma("unroll")                                                      \
        for (int _i = 0; _i < 4; _i++)                                         \
            wreg[_i] = *(const float4*)(Wg + (size_t)(rowL + 32 * _i) * KDIM   \
                                        + (ktv) * KT + col4 * 4);              \
    } while (0)

    #define STS_W(buf) do {                                                    \
        _Pragma("unroll")                                                      \
        for (int _i = 0; _i < 4; _i++) {                                       \
            __half2 _h0 = __floats2half2_rn(wreg[_i].x, wreg[_i].y);           \
            __half2 _h1 = __floats2half2_rn(wreg[_i].z, wreg[_i].w);           \
            uint32_t _ad = sbase + WF_OFF + (uint32_t)(buf) * TILE_B           \
                         + (uint32_t)((rowL + 32 * _i) * SROW + col4 * 4) * 2; \
            asm volatile("st.shared.v2.u32 [%0], {%1, %2};" :: "r"(_ad),       \
                         "r"(*(uint32_t*)&_h0), "r"(*(uint32_t*)&_h1));        \
        }                                                                      \
    } while (0)

    // Prologue: A stages 0..3; W slots 0,1 + regs hold W(2)
    ISSUE_A(0, 0); CP_COMMIT();
    ISSUE_A(1, 1); CP_COMMIT();
    ISSUE_A(2, 2); CP_COMMIT();
    ISSUE_A(3, 3); CP_COMMIT();
    LOAD_W(0); STS_W(0);
    LOAD_W(1); STS_W(1);
    LOAD_W(2);

    // ldmatrix lane addressing
    const int g = lane >> 3, rin = lane & 7;
    const int rowA = M0 + (g & 1) * 8 + rin;
    const int colA = (g >> 1) * 8;
    const int rowB = N0 + (g >> 1) * 8 + rin;
    const int colB = (g & 1) * 8;

    float acc[2][4][4];
    #pragma unroll
    for (int i = 0; i < 2; i++)
        #pragma unroll
        for (int j = 0; j < 4; j++)
            #pragma unroll
            for (int k = 0; k < 4; k++) acc[i][j][k] = 0.0f;

    uint32_t aF[2][2][4], bF[2][2][4];

    #define LOADH(hh, buf, bAv, bWv) do {                                      \
        const int _kc = (hh) * 16;                                             \
        _Pragma("unroll")                                                      \
        for (int _mi = 0; _mi < 2; _mi++)                                      \
            ldsm_x4(aF[buf][_mi],                                              \
                    (bAv) + (uint32_t)((rowA + _mi * 16) * SROW + _kc + colA) * 2); \
        _Pragma("unroll")                                                      \
        for (int _j = 0; _j < 2; _j++)                                         \
            ldsm_x4(bF[buf][_j],                                               \
                    (bWv) + (uint32_t)((rowB + _j * 16) * SROW + _kc + colB) * 2);  \
    } while (0)

    #define COMPUTE_TILE(slotA, slotW) do {                                    \
        const uint32_t _bA = sbase + (uint32_t)(slotA) * TILE_B;               \
        const uint32_t _bW = sbase + WF_OFF + (uint32_t)(slotW) * TILE_B;      \
        LOADH(0, 0, _bA, _bW);                                                 \
        _Pragma("unroll")                                                      \
        for (int _h = 0; _h < 4; _h++) {                                       \
            const int _cur = _h & 1;                                           \
            if (_h < 3) LOADH(_h + 1, _cur ^ 1, _bA, _bW);                     \
            _Pragma("unroll")                                                  \
            for (int _mi = 0; _mi < 2; _mi++)                                  \
                _Pragma("unroll")                                              \
                for (int _nj = 0; _nj < 4; _nj++) {                            \
                    const int _jj = _nj >> 1, _pp = (_nj & 1) * 2;             \
                    mma16816h(acc[_mi][_nj], aF[_cur][_mi],                    \
                              bF[_cur][_jj][_pp], bF[_cur][_jj][_pp + 1]);     \
                }                                                              \
        }                                                                      \
    } while (0)

    int sA0 = 0, sA1 = 1, iA0 = 4, iA1 = 5;
    for (int kt = 0; kt < NT; kt += 2) {
        if (kt + 2 >= NT) cp_wait<0>(); else cp_wait<2>();
        __syncthreads();   // publishes A[kt],A[kt+1] + W slots (kt&3),(kt+1)&3
        if (kt + 4 < NT) { ISSUE_A(kt + 4, iA0); CP_COMMIT(); }
        if (kt + 5 < NT) { ISSUE_A(kt + 5, iA1); CP_COMMIT(); }

        COMPUTE_TILE(sA0, kt & 3);
        if (kt + 2 < NT) {
            STS_W((kt + 2) & 3);   // wreg holds W(kt+2)
            LOAD_W(kt + 3);
        }
        COMPUTE_TILE(sA1, (kt + 1) & 3);
        if (kt + 2 < NT) STS_W((kt + 3) & 3);
        if (kt + 4 < NT) LOAD_W(kt + 4);

        sA0 += 2; if (sA0 >= NASLOT) sA0 -= NASLOT;
        sA1 += 2; if (sA1 >= NASLOT) sA1 -= NASLOT;
        iA0 += 2; if (iA0 >= NASLOT) iA0 -= NASLOT;
        iA1 += 2; if (iA1 >= NASLOT) iA1 -= NASLOT;
    }

    // epilogue: bias + tanh -> fp16 Ch (+ fp32 C if requested)
    const int r0l = lane >> 2;
    const int c0l = 2 * (lane & 3);
    #pragma unroll
    for (int mi = 0; mi < 2; mi++) {
        #pragma unroll
        for (int nj = 0; nj < 4; nj++) {
            const int gnl = N0 + nj * 8 + c0l;
            const float b0 = biasS[gnl], b1 = biasS[gnl + 1];
            const int gm0 = m0 + M0 + mi * 16 + r0l;
            float v00 = tanhf(acc[mi][nj][0] + b0);
            float v01 = tanhf(acc[mi][nj][1] + b1);
            float v10 = tanhf(acc[mi][nj][2] + b0);
            float v11 = tanhf(acc[mi][nj][3] + b1);
            *(__half2*)(Ch + (size_t)gm0 * DIM + n0 + gnl) =
                __floats2half2_rn(v00, v01);
            *(__half2*)(Ch + (size_t)(gm0 + 8) * DIM + n0 + gnl) =
                __floats2half2_rn(v10, v11);
            if (C != nullptr) {
                *(float2*)(C + (size_t)gm0 * DIM + n0 + gnl) = make_float2(v00, v01);
                *(float2*)(C + (size_t)(gm0 + 8) * DIM + n0 + gnl) = make_float2(v10, v11);
            }
        }
    }
}

// ---------------------------------------------------------------------------
// 4) Fused fidelity: 10 dots (fp32, uint4 loads) + last-block finalize.
// ---------------------------------------------------------------------------
__global__ void fid_kernel(const __half* __restrict__ a1,
                           const __half* __restrict__ a2,
                           const __half* __restrict__ a3,
                           const __half* __restrict__ a4,
                           float* __restrict__ wout) {
    float s[10];
    #pragma unroll
    for (int k = 0; k < 10; k++) s[k] = 0.0f;
    const int stride = gridDim.x * blockDim.x;
    // 8 halves (one uint4) per array per iteration
    for (int idx = blockIdx.x * blockDim.x + threadIdx.x; idx < OUTN / 8; idx += stride) {
        uint4 u1 = ((const uint4*)a1)[idx];
        uint4 u2 = ((const uint4*)a2)[idx];
        uint4 u3 = ((const uint4*)a3)[idx];
        uint4 u4 = ((const uint4*)a4)[idx];
        const uint32_t* p1 = (const uint32_t*)&u1;
        const uint32_t* p2 = (const uint32_t*)&u2;
        const uint32_t* p3 = (const uint32_t*)&u3;
        const uint32_t* p4 = (const uint32_t*)&u4;
        #pragma unroll
        for (int q = 0; q < 4; q++) {
            float2 f1 = __half22float2(*(const __half2*)&p1[q]);
            float2 f2 = __half22float2(*(const __half2*)&p2[q]);
            float2 f3 = __half22float2(*(const __half2*)&p3[q]);
            float2 f4 = __half22float2(*(const __half2*)&p4[q]);
            s[0] += f1.x * f1.x + f1.y * f1.y;
            s[1] += f1.x * f2.x + f1.y * f2.y;
            s[2] += f1.x * f3.x + f1.y * f3.y;
            s[3] += f1.x * f4.x + f1.y * f4.y;
            s[4] += f2.x * f2.x + f2.y * f2.y;
            s[5] += f2.x * f3.x + f2.y * f3.y;
            s[6] += f2.x * f4.x + f2.y * f4.y;
            s[7] += f3.x * f3.x + f3.y * f3.y;
            s[8] += f3.x * f4.x + f3.y * f4.y;
            s[9] += f4.x * f4.x + f4.y * f4.y;
        }
    }
    #pragma unroll
    for (int k = 0; k < 10; k++)
        #pragma unroll
        for (int off = 16; off > 0; off >>= 1)
            s[k] += __shfl_down_sync(0xFFFFFFFFu, s[k], off);
    __shared__ float ws[8][10];
    const int wid = threadIdx.x >> 5, lid = threadIdx.x & 31;
    if (lid == 0)
        #pragma unroll
        for (int k = 0; k < 10; k++) ws[wid][k] = s[k];
    __syncthreads();

    __shared__ unsigned int lastFlag;
    if (threadIdx.x == 0) {
        #pragma unroll
        for (int k = 0; k < 10; k++) {
            float acc = 0.0f;
            for (int w = 0; w < 8; w++) acc += ws[w][k];
            g_partials[blockIdx.x * 10 + k] = acc;
        }
        __threadfence();
        unsigned int v = atomicAdd(&g_ticket, 1u);
        lastFlag = (v == gridDim.x - 1) ? 1u : 0u;
    }
    __syncthreads();
    if (lastFlag == 0u) return;

    __shared__ double dots[10];
    #pragma unroll
    for (int pass = 0; pass < 2; pass++) {
        int d = pass == 0 ? wid : (wid < 2 ? 8 + wid : -1);
        if (pass == 1 && wid >= 2) break;
        if (d >= 0 && d < 10) {
            double acc = 0.0;
            for (int p = lid; p < FID_BLOCKS; p += 32)
                acc += (double)g_partials[p * 10 + d];
            #pragma unroll
            for (int off = 16; off > 0; off >>= 1)
                acc += __shfl_down_sync(0xFFFFFFFFu, acc, off);
            if (lid == 0) dots[d] = acc;
        }
    }
    __syncthreads();
    if (threadIdx.x < 16) {
        int i = threadIdx.x >> 2, j = threadIdx.x & 3;
        int ii = i < j ? i : j, jj = i < j ? j : i;
        const int base[4] = {0, 4, 7, 9};
        double dij = dots[base[ii] + (jj - ii)];
        double dii = dots[base[ii]];
        double djj = dots[base[jj]];
        double ni = sqrt(dii) + 1e-12;
        double nj = sqrt(djj) + 1e-12;
        double sh = dij / (ni * nj);
        double fid = sh * sh;
        wout[threadIdx.x] = (fid >= 0.8 && i != j) ? 1.0f : 0.0f;
    }
    if (threadIdx.x == 0) g_ticket = 0u;   // reset for next graph replay
}

// ---------------------------------------------------------------------------
// kernel_launch
//   0 conv, 1 attn_layer1, 2 gemm1, 3 gemm2, 4 gemm3, 5 fid <- profiled
// ---------------------------------------------------------------------------
extern "C" void kernel_launch(void* const* d_in, const int* in_sizes, int n_in,
                              void* d_out, int out_size) {
    const float* x   = (const float*)d_in[0];
    const float* cw  = (const float*)d_in[1];
    const float* cb  = (const float*)d_in[2];
    const float* rot = (const float*)d_in[3];
    const float* ent = (const float*)d_in[4];
    const float* W1  = (const float*)d_in[5];
    const float* b1  = (const float*)d_in[6];
    const float* W2  = (const float*)d_in[7];
    const float* b2  = (const float*)d_in[8];
    const float* W3  = (const float*)d_in[9];
    const float* b3  = (const float*)d_in[10];
    const float* W4  = (const float*)d_in[11];
    const float* b4  = (const float*)d_in[12];
    float* out = (float*)d_out;

    float* gc;
    __half* ah;
    cudaGetSymbolAddress((void**)&gc, g_c);
    cudaGetSymbolAddress((void**)&ah, g_ah);

    cudaFuncSetAttribute(gemm_mma_kernel,
                         cudaFuncAttributeMaxDynamicSharedMemorySize, SMEM_REQ);

    dim3 ggrid(DIM / 128, BB / 128);  // (32, 4)

    conv_kernel<<<BB, 256>>>(x, cw, cb, gc);                         // 0
    attn_layer1_kernel<<<1024, 256>>>(gc, rot, ent, W1, b1,          // 1
                                      ah + 0 * (size_t)OUTN);
    gemm_mma_kernel<<<ggrid, 512, SMEM_REQ>>>(                       // 2
        ah + 0 * (size_t)OUTN, W2, b2,
        nullptr, ah + 1 * (size_t)OUTN);
    gemm_mma_kernel<<<ggrid, 512, SMEM_REQ>>>(                       // 3
        ah + 1 * (size_t)OUTN, W3, b3,
        nullptr, ah + 2 * (size_t)OUTN);
    gemm_mma_kernel<<<ggrid, 512, SMEM_REQ>>>(                       // 4
        ah + 2 * (size_t)OUTN, W4, b4,
        out, ah + 3 * (size_t)OUTN);
    fid_kernel<<<FID_BLOCKS, 256>>>(ah + 0 * (size_t)OUTN,           // 5 <- profiled
                                    ah + 1 * (size_t)OUTN,
                                    ah + 2 * (size_t)OUTN,
                                    ah + 3 * (size_t)OUTN,
                                    out + OUTN);
}